// round 14
// baseline (speedup 1.0000x reference)
#include <cuda_runtime.h>
#include <cuda_bf16.h>
#include <cstdint>

__device__ double g_acc[2] = {0.0, 0.0};
__device__ unsigned int g_done = 0u;
__device__ unsigned int g_next = 0u;

#define NTHREADS 256
#define NBLOCKS  608
#define STAGE_BYTES 12288u      // 6KB pred_pose + 6KB target_pose
#define NSTAGES 4u

__device__ __forceinline__ float fsqrt_approx(float x) {
    float r;
    asm("sqrt.approx.f32 %0, %1;" : "=f"(r) : "f"(x));
    return r;
}

__device__ __forceinline__ uint32_t smem_u32(const void* p) {
    uint32_t a;
    asm("{ .reg .u64 t; cvta.to.shared.u64 t, %1; cvt.u32.u64 %0, t; }" : "=r"(a) : "l"(p));
    return a;
}

__device__ __forceinline__ void cp16(uint32_t dst, const void* src) {
    asm volatile("cp.async.cg.shared.global [%0], [%1], 16;"
                 :: "r"(dst), "l"(src) : "memory");
}
__device__ __forceinline__ void cp_commit() {
    asm volatile("cp.async.commit_group;" ::: "memory");
}
__device__ __forceinline__ void cp_wait2() {
    asm volatile("cp.async.wait_group 2;" ::: "memory");
}

extern __shared__ float4 s_pose[];   // NSTAGES * 768 float4 = 48KB

// stage layout: [0,6144) pred_pose, [6144,12288) target_pose; chunk = 256 rows
__device__ __forceinline__ void fill_stage(
    uint32_t st, const float* pp, const float* tp, int c, int tid)
{
    const float4* gp = (const float4*)pp + 384ull * (size_t)c;
    const float4* gt = (const float4*)tp + 384ull * (size_t)c;
    cp16(st + (uint32_t)tid * 16u,          gp + tid);
    cp16(st + 6144u + (uint32_t)tid * 16u,  gt + tid);
    if (tid < 128) {
        cp16(st + (uint32_t)(256 + tid) * 16u,         gp + 256 + tid);
        cp16(st + 6144u + (uint32_t)(256 + tid) * 16u, gt + 256 + tid);
    }
}

__global__ __launch_bounds__(NTHREADS, 4) void pose_loss_kernel(
    const float* __restrict__ pp,
    const float* __restrict__ pc,
    const float* __restrict__ tp,
    const float* __restrict__ tc,
    float* __restrict__ out,
    int B)
{
    const unsigned int nChunks = (unsigned)(B >> 8);
    const int tid = threadIdx.x;

    __shared__ int   s_init[4];
    __shared__ int   s_steal[2];
    __shared__ float shp[8];
    __shared__ float shc[8];
    __shared__ bool  is_last;

    const uint32_t sbase = smem_u32(s_pose);

    // ---- prologue: steal 4 chain positions ----
    if (tid == 0) {
        #pragma unroll
        for (int k = 0; k < 4; k++) {
            unsigned a = atomicAdd(&g_next, 1u);
            s_init[k] = (a < nChunks) ? (int)a : -1;
        }
        s_steal[0] = s_init[3];    // chunk for chain position 3 (filled at iter 0)
    }
    __syncthreads();
    int cur = s_init[0], n1 = s_init[1], n2 = s_init[2];

    // fill stages 0..2 with positions 0..2 (one commit group each)
    if (cur >= 0) fill_stage(sbase,                   pp, tp, cur, tid);
    cp_commit();
    if (n1  >= 0) fill_stage(sbase + STAGE_BYTES,     pp, tp, n1,  tid);
    cp_commit();
    if (n2  >= 0) fill_stage(sbase + 2u * STAGE_BYTES, pp, tp, n2, tid);
    cp_commit();

    float pose_s = 0.f, cls_s = 0.f;
    const float L = 0.05f;
    int i = 0;

    while (cur >= 0) {
        // class loads for current chunk: direct, coalesced; fly across the wait
        size_t b = ((size_t)cur << 8) + (size_t)tid;
        const float4* pc4 = (const float4*)pc + 4ull * b;
        const float4* tc4 = (const float4*)tc + 4ull * b;
        float4 x0 = __ldcs(pc4 + 0), x1 = __ldcs(pc4 + 1),
               x2 = __ldcs(pc4 + 2), x3 = __ldcs(pc4 + 3);
        float4 y0 = __ldcs(tc4 + 0), y1 = __ldcs(tc4 + 1),
               y2 = __ldcs(tc4 + 2), y3 = __ldcs(tc4 + 3);

        // pending groups here: positions {i, i+1, i+2} -> wait leaves 2 newest
        cp_wait2();
        __syncthreads();   // orders: stage i ready; iter i-1 reads of stage (i-1)%4
                           // done (fill target below); s_steal[i&1] visible

        // fill position i+3 into stage (i+3)%4 == (i-1)%4 (read at iter i-1)
        int n3 = s_steal[i & 1];
        if (n3 >= 0)
            fill_stage(sbase + ((uint32_t)(i + 3) & 3u) * STAGE_BYTES, pp, tp, n3, tid);
        cp_commit();       // exactly one commit per iteration (maybe empty)

        // steal position i+4 for next iteration (hidden under compute)
        if (tid == 0) {
            int v = -1;
            if (n3 >= 0) {
                unsigned a = atomicAdd(&g_next, 1u);
                if (a < nChunks) v = (int)a;
            }
            s_steal[(i + 1) & 1] = v;
        }

        // ---- compute on stage i%4 ----
        const float* spf = (const float*)(s_pose + (size_t)(i & 3) * 768u);
        const float2* mp = (const float2*)(spf + 6 * tid);
        const float2* mt = (const float2*)(spf + 1536 + 6 * tid);
        float2 a0 = mp[0], a1 = mp[1], a2 = mp[2];
        float2 b0 = mt[0], b1 = mt[1], b2 = mt[2];

        float sy1, cy1, sp1, cp1, sr1, cr1;
        __sincosf(a0.x, &sy1, &cy1);
        __sincosf(a0.y, &sp1, &cp1);
        __sincosf(a1.x, &sr1, &cr1);
        float sy2, cy2, sp2, cp2, sr2, cr2;
        __sincosf(b0.x, &sy2, &cy2);
        __sincosf(b0.y, &sp2, &cp2);
        __sincosf(b1.x, &sr2, &cr2);

        // class MSE in the MUFU shadow
        {
            float d;
            d = x0.x - y0.x; cls_s = fmaf(d, d, cls_s);
            d = x0.y - y0.y; cls_s = fmaf(d, d, cls_s);
            d = x0.z - y0.z; cls_s = fmaf(d, d, cls_s);
            d = x0.w - y0.w; cls_s = fmaf(d, d, cls_s);
            d = x1.x - y1.x; cls_s = fmaf(d, d, cls_s);
            d = x1.y - y1.y; cls_s = fmaf(d, d, cls_s);
            d = x1.z - y1.z; cls_s = fmaf(d, d, cls_s);
            d = x1.w - y1.w; cls_s = fmaf(d, d, cls_s);
            d = x2.x - y2.x; cls_s = fmaf(d, d, cls_s);
            d = x2.y - y2.y; cls_s = fmaf(d, d, cls_s);
            d = x2.z - y2.z; cls_s = fmaf(d, d, cls_s);
            d = x2.w - y2.w; cls_s = fmaf(d, d, cls_s);
            d = x3.x - y3.x; cls_s = fmaf(d, d, cls_s);
            d = x3.y - y3.y; cls_s = fmaf(d, d, cls_s);
            d = x3.z - y3.z; cls_s = fmaf(d, d, cls_s);
            d = x3.w - y3.w; cls_s = fmaf(d, d, cls_s);
        }

        float D0 = cy1*cp1                 - cy2*cp2;
        float D1 = (cy1*sp1*sr1 - sy1*cr1) - (cy2*sp2*sr2 - sy2*cr2);
        float D2 = (cy1*sp1*cr1 + sy1*sr1) - (cy2*sp2*cr2 + sy2*sr2);
        float D3 = sy1*cp1                 - sy2*cp2;
        float D4 = (sy1*sp1*sr1 + cy1*cr1) - (sy2*sp2*sr2 + cy2*cr2);
        float D5 = (sy1*sp1*cr1 - cy1*sr1) - (sy2*sp2*cr2 - cy2*sr2);
        float D6 = -sp1                    + sp2;
        float D7 = cp1*sr1                 - cp2*sr2;
        float D8 = cp1*cr1                 - cp2*cr2;
        D0 *= L; D1 *= L; D2 *= L;
        D3 *= L; D4 *= L; D5 *= L;
        D6 *= L; D7 *= L; D8 *= L;

        float dt0 = a1.y - b1.y;
        float dt1 = a2.x - b2.x;
        float dt2 = a2.y - b2.y;

        float s2 = 0.f;
        #pragma unroll
        for (int ix = 0; ix < 2; ix++) {
            float fx = ix ? 1.f : -1.f;
            #pragma unroll
            for (int iy = 0; iy < 2; iy++) {
                float fy = iy ? 1.f : -1.f;
                #pragma unroll
                for (int iz = 0; iz < 2; iz++) {
                    float fz = iz ? 1.f : -1.f;
                    float vx = fmaf(fx, D0, fmaf(fy, D1, fmaf(fz, D2, dt0)));
                    float vy = fmaf(fx, D3, fmaf(fy, D4, fmaf(fz, D5, dt1)));
                    float vz = fmaf(fx, D6, fmaf(fy, D7, fmaf(fz, D8, dt2)));
                    float n2l = fmaf(vx, vx, fmaf(vy, vy, vz * vz));
                    s2 += fsqrt_approx(n2l);
                }
            }
        }
        pose_s = fmaf(s2, 0.125f, pose_s);

        cur = n1; n1 = n2; n2 = n3; i++;
    }

    // ---- reduce ----
    #pragma unroll
    for (int o = 16; o > 0; o >>= 1) {
        pose_s += __shfl_down_sync(0xffffffffu, pose_s, o);
        cls_s  += __shfl_down_sync(0xffffffffu, cls_s,  o);
    }
    int lane = tid & 31;
    int w    = tid >> 5;
    if (lane == 0) { shp[w] = pose_s; shc[w] = cls_s; }
    __syncthreads();

    if (tid == 0) {
        float ap = 0.f, ac = 0.f;
        #pragma unroll
        for (int k = 0; k < 8; k++) { ap += shp[k]; ac += shc[k]; }
        atomicAdd(&g_acc[0], (double)ap);
        atomicAdd(&g_acc[1], (double)ac);
        __threadfence();
        unsigned int prev = atomicAdd(&g_done, 1u);
        is_last = (prev == gridDim.x - 1u);
    }
    __syncthreads();

    if (is_last && tid == 0) {
        double pose_mean = g_acc[0] / (double)B;
        double cls_mean  = g_acc[1] / ((double)B * 16.0);
        out[0] = (float)(pose_mean + cls_mean);
        out[1] = (float)pose_mean;
        out[2] = (float)cls_mean;
        g_acc[0] = 0.0;
        g_acc[1] = 0.0;
        g_next   = 0u;
        __threadfence();
        g_done = 0u;
    }
}

extern "C" void kernel_launch(void* const* d_in, const int* in_sizes, int n_in,
                              void* d_out, int out_size) {
    const float* pp = (const float*)d_in[0];
    const float* pc = (const float*)d_in[1];
    const float* tp = (const float*)d_in[2];
    const float* tc = (const float*)d_in[3];
    int B = in_sizes[0] / 6;

    const unsigned smem_bytes = NSTAGES * STAGE_BYTES;   // 48KB
    cudaFuncSetAttribute(pose_loss_kernel,
                         cudaFuncAttributeMaxDynamicSharedMemorySize,
                         (int)smem_bytes);
    pose_loss_kernel<<<NBLOCKS, NTHREADS, smem_bytes>>>(
        pp, pc, tp, tc, (float*)d_out, B);
}

// round 15
// speedup vs baseline: 1.3086x; 1.3086x over previous
#include <cuda_runtime.h>
#include <cuda_bf16.h>
#include <cstdint>

__device__ double g_acc[2] = {0.0, 0.0};
__device__ unsigned int g_done = 0u;
__device__ unsigned int g_next = 0u;

#define NTHREADS 256
#define NBLOCKS  608

__device__ __forceinline__ float fsqrt_approx(float x) {
    float r;
    asm("sqrt.approx.f32 %0, %1;" : "=f"(r) : "f"(x));
    return r;
}

__device__ __forceinline__ uint32_t smem_u32(const void* p) {
    uint32_t a;
    asm("{ .reg .u64 t; cvta.to.shared.u64 t, %1; cvt.u32.u64 %0, t; }" : "=r"(a) : "l"(p));
    return a;
}

__device__ __forceinline__ void cp16(uint32_t dst, const void* src) {
    asm volatile("cp.async.cg.shared.global [%0], [%1], 16;"
                 :: "r"(dst), "l"(src) : "memory");
}
__device__ __forceinline__ void cp_commit() {
    asm volatile("cp.async.commit_group;" ::: "memory");
}
__device__ __forceinline__ void cp_wait1() {
    asm volatile("cp.async.wait_group 1;" ::: "memory");
}

// stage layout: [0,6144) pred_pose chunk, [6144,12288) target_pose chunk
// one chunk = 256 rows * 24B = 6144B = 384 float4 per tensor
__device__ __forceinline__ void fill_stage(
    uint32_t st, const float* pp, const float* tp, int c, int tid)
{
    const float4* gp = (const float4*)pp + 384ull * (size_t)c;
    const float4* gt = (const float4*)tp + 384ull * (size_t)c;
    cp16(st + (uint32_t)tid * 16u,          gp + tid);
    cp16(st + 6144u + (uint32_t)tid * 16u,  gt + tid);
    if (tid < 128) {
        cp16(st + (uint32_t)(256 + tid) * 16u,         gp + 256 + tid);
        cp16(st + 6144u + (uint32_t)(256 + tid) * 16u, gt + 256 + tid);
    }
}

__global__ __launch_bounds__(NTHREADS, 4) void pose_loss_kernel(
    const float* __restrict__ pp,   // pred_pose  [B,6]
    const float* __restrict__ pc,   // pred_class [B,16]
    const float* __restrict__ tp,   // target_pose[B,6]
    const float* __restrict__ tc,   // target_class[B,16]
    float* __restrict__ out,
    int B)
{
    const unsigned int nChunks = (unsigned)(B >> 8);   // 256 rows per chunk
    const int tid = threadIdx.x;

    __shared__ float4 s_pose[2][768];     // 2 stages x 12KB
    __shared__ int   s_idx[2];
    __shared__ int   s_steal;
    __shared__ float shp[8];
    __shared__ float shc[8];
    __shared__ bool  is_last;

    const uint32_t sbase = smem_u32(&s_pose[0][0]);

    // ---- steal first two chunks ----
    if (tid == 0) {
        unsigned a = atomicAdd(&g_next, 1u);
        s_idx[0] = (a < nChunks) ? (int)a : -1;
        unsigned b2 = atomicAdd(&g_next, 1u);
        s_idx[1] = (b2 < nChunks) ? (int)b2 : -1;
    }
    __syncthreads();
    int cur = s_idx[0];
    int nxt = s_idx[1];

    if (cur >= 0) fill_stage(sbase,          pp, tp, cur, tid);
    cp_commit();
    if (nxt >= 0) fill_stage(sbase + 12288u, pp, tp, nxt, tid);
    cp_commit();

    float pose_s = 0.f, cls_s = 0.f;
    const float L = 0.05f;
    int s = 0;

    // loop-invariant smem row pointers (per stage)
    const float* sp0 = (const float*)&s_pose[0][0];
    const float* sp1 = (const float*)&s_pose[1][0];

    while (cur >= 0) {
        // class loads for current chunk: direct, coalesced, fly across the wait
        size_t b = ((size_t)cur << 8) + (size_t)tid;
        const float4* pc4 = (const float4*)pc + 4ull * b;
        const float4* tc4 = (const float4*)tc + 4ull * b;
        float4 x0 = __ldcs(pc4 + 0), x1 = __ldcs(pc4 + 1),
               x2 = __ldcs(pc4 + 2), x3 = __ldcs(pc4 + 3);
        float4 y0 = __ldcs(tc4 + 0), y1 = __ldcs(tc4 + 1),
               y2 = __ldcs(tc4 + 2), y3 = __ldcs(tc4 + 3);

        cp_wait1();           // this chunk's pose staged
        __syncthreads();

        // steal chunk-after-next while everyone computes (hidden ATOMG)
        if (tid == 0) {
            int n2 = -1;
            if (nxt >= 0) {
                unsigned a = atomicAdd(&g_next, 1u);
                if (a < nChunks) n2 = (int)a;
            }
            s_steal = n2;
        }

        // pose row from smem (24B/thread, <=2-way LDS conflict)
        const float* spf = s ? sp1 : sp0;
        const float2* mp = (const float2*)(spf + 6 * tid);
        const float2* mt = (const float2*)(spf + 1536 + 6 * tid);
        float2 a0 = mp[0], a1 = mp[1], a2 = mp[2];
        float2 b0 = mt[0], b1 = mt[1], b2 = mt[2];

        float sy1, cy1, sp1v, cp1v, sr1, cr1;
        __sincosf(a0.x, &sy1, &cy1);
        __sincosf(a0.y, &sp1v, &cp1v);
        __sincosf(a1.x, &sr1, &cr1);
        float sy2, cy2, sp2v, cp2v, sr2, cr2;
        __sincosf(b0.x, &sy2, &cy2);
        __sincosf(b0.y, &sp2v, &cp2v);
        __sincosf(b1.x, &sr2, &cr2);

        // class MSE in the MUFU shadow
        {
            float d;
            d = x0.x - y0.x; cls_s = fmaf(d, d, cls_s);
            d = x0.y - y0.y; cls_s = fmaf(d, d, cls_s);
            d = x0.z - y0.z; cls_s = fmaf(d, d, cls_s);
            d = x0.w - y0.w; cls_s = fmaf(d, d, cls_s);
            d = x1.x - y1.x; cls_s = fmaf(d, d, cls_s);
            d = x1.y - y1.y; cls_s = fmaf(d, d, cls_s);
            d = x1.z - y1.z; cls_s = fmaf(d, d, cls_s);
            d = x1.w - y1.w; cls_s = fmaf(d, d, cls_s);
            d = x2.x - y2.x; cls_s = fmaf(d, d, cls_s);
            d = x2.y - y2.y; cls_s = fmaf(d, d, cls_s);
            d = x2.z - y2.z; cls_s = fmaf(d, d, cls_s);
            d = x2.w - y2.w; cls_s = fmaf(d, d, cls_s);
            d = x3.x - y3.x; cls_s = fmaf(d, d, cls_s);
            d = x3.y - y3.y; cls_s = fmaf(d, d, cls_s);
            d = x3.z - y3.z; cls_s = fmaf(d, d, cls_s);
            d = x3.w - y3.w; cls_s = fmaf(d, d, cls_s);
        }

        // D = R_pred - R_gt, pre-scaled by L
        float D0 = cy1*cp1v                  - cy2*cp2v;
        float D1 = (cy1*sp1v*sr1 - sy1*cr1)  - (cy2*sp2v*sr2 - sy2*cr2);
        float D2 = (cy1*sp1v*cr1 + sy1*sr1)  - (cy2*sp2v*cr2 + sy2*sr2);
        float D3 = sy1*cp1v                  - sy2*cp2v;
        float D4 = (sy1*sp1v*sr1 + cy1*cr1)  - (sy2*sp2v*sr2 + cy2*cr2);
        float D5 = (sy1*sp1v*cr1 - cy1*sr1)  - (sy2*sp2v*cr2 - cy2*sr2);
        float D6 = -sp1v                     + sp2v;
        float D7 = cp1v*sr1                  - cp2v*sr2;
        float D8 = cp1v*cr1                  - cp2v*cr2;
        D0 *= L; D1 *= L; D2 *= L;
        D3 *= L; D4 *= L; D5 *= L;
        D6 *= L; D7 *= L; D8 *= L;

        float dt0 = a1.y - b1.y;
        float dt1 = a2.x - b2.x;
        float dt2 = a2.y - b2.y;

        float s2 = 0.f;
        #pragma unroll
        for (int ix = 0; ix < 2; ix++) {
            float fx = ix ? 1.f : -1.f;
            #pragma unroll
            for (int iy = 0; iy < 2; iy++) {
                float fy = iy ? 1.f : -1.f;
                #pragma unroll
                for (int iz = 0; iz < 2; iz++) {
                    float fz = iz ? 1.f : -1.f;
                    float vx = fmaf(fx, D0, fmaf(fy, D1, fmaf(fz, D2, dt0)));
                    float vy = fmaf(fx, D3, fmaf(fy, D4, fmaf(fz, D5, dt1)));
                    float vz = fmaf(fx, D6, fmaf(fy, D7, fmaf(fz, D8, dt2)));
                    float n2 = fmaf(vx, vx, fmaf(vy, vy, vz * vz));
                    s2 += fsqrt_approx(n2);
                }
            }
        }
        pose_s = fmaf(s2, 0.125f, pose_s);

        __syncthreads();      // stage reads done; s_steal visible

        int n2 = s_steal;
        if (n2 >= 0) fill_stage(sbase + (uint32_t)s * 12288u, pp, tp, n2, tid);
        cp_commit();          // exactly one commit per iteration (maybe empty)

        cur = nxt; nxt = n2; s ^= 1;
    }

    // ---- reduce ----
    #pragma unroll
    for (int o = 16; o > 0; o >>= 1) {
        pose_s += __shfl_down_sync(0xffffffffu, pose_s, o);
        cls_s  += __shfl_down_sync(0xffffffffu, cls_s,  o);
    }
    int lane = tid & 31;
    int w    = tid >> 5;
    if (lane == 0) { shp[w] = pose_s; shc[w] = cls_s; }
    __syncthreads();

    if (tid == 0) {
        float ap = 0.f, ac = 0.f;
        #pragma unroll
        for (int k = 0; k < 8; k++) { ap += shp[k]; ac += shc[k]; }
        atomicAdd(&g_acc[0], (double)ap);
        atomicAdd(&g_acc[1], (double)ac);
        __threadfence();
        unsigned int prev = atomicAdd(&g_done, 1u);
        is_last = (prev == gridDim.x - 1u);
    }
    __syncthreads();

    if (is_last && tid == 0) {
        double pose_mean = g_acc[0] / (double)B;
        double cls_mean  = g_acc[1] / ((double)B * 16.0);
        out[0] = (float)(pose_mean + cls_mean);
        out[1] = (float)pose_mean;
        out[2] = (float)cls_mean;
        g_acc[0] = 0.0;
        g_acc[1] = 0.0;
        g_next   = 0u;          // reset work counter for next replay
        __threadfence();
        g_done = 0u;
    }
}

extern "C" void kernel_launch(void* const* d_in, const int* in_sizes, int n_in,
                              void* d_out, int out_size) {
    const float* pp = (const float*)d_in[0];
    const float* pc = (const float*)d_in[1];
    const float* tp = (const float*)d_in[2];
    const float* tc = (const float*)d_in[3];
    int B = in_sizes[0] / 6;

    pose_loss_kernel<<<NBLOCKS, NTHREADS>>>(pp, pc, tp, tc, (float*)d_out, B);
}

// round 16
// speedup vs baseline: 1.3101x; 1.0012x over previous
#include <cuda_runtime.h>
#include <cuda_bf16.h>
#include <cstdint>

__device__ double g_acc[2] = {0.0, 0.0};
__device__ unsigned int g_done = 0u;
__device__ unsigned int g_next = 0u;

#define NTHREADS 256
#define NBLOCKS  608

__device__ __forceinline__ float fsqrt_approx(float x) {
    float r;
    asm("sqrt.approx.f32 %0, %1;" : "=f"(r) : "f"(x));
    return r;
}

__device__ __forceinline__ uint32_t smem_u32(const void* p) {
    uint32_t a;
    asm("{ .reg .u64 t; cvta.to.shared.u64 t, %1; cvt.u32.u64 %0, t; }" : "=r"(a) : "l"(p));
    return a;
}

__device__ __forceinline__ void cp16(uint32_t dst, const void* src) {
    asm volatile("cp.async.cg.shared.global [%0], [%1], 16;"
                 :: "r"(dst), "l"(src) : "memory");
}
__device__ __forceinline__ void cp_commit() {
    asm volatile("cp.async.commit_group;" ::: "memory");
}
__device__ __forceinline__ void cp_wait1() {
    asm volatile("cp.async.wait_group 1;" ::: "memory");
}

// stage layout: [0,6144) pred_pose chunk, [6144,12288) target_pose chunk
// one chunk = 256 rows * 24B = 6144B = 384 float4 per tensor
__device__ __forceinline__ void fill_stage(
    uint32_t st, const float* pp, const float* tp, int c, int tid)
{
    const float4* gp = (const float4*)pp + 384ull * (size_t)c;
    const float4* gt = (const float4*)tp + 384ull * (size_t)c;
    cp16(st + (uint32_t)tid * 16u,          gp + tid);
    cp16(st + 6144u + (uint32_t)tid * 16u,  gt + tid);
    if (tid < 128) {
        cp16(st + (uint32_t)(256 + tid) * 16u,         gp + 256 + tid);
        cp16(st + 6144u + (uint32_t)(256 + tid) * 16u, gt + 256 + tid);
    }
}

__global__ __launch_bounds__(NTHREADS, 4) void pose_loss_kernel(
    const float* __restrict__ pp,   // pred_pose  [B,6]
    const float* __restrict__ pc,   // pred_class [B,16]
    const float* __restrict__ tp,   // target_pose[B,6]
    const float* __restrict__ tc,   // target_class[B,16]
    float* __restrict__ out,
    int B)
{
    const unsigned int nChunks = (unsigned)(B >> 8);   // 256 rows per chunk
    const int tid = threadIdx.x;

    __shared__ float4 s_pose[2][768];     // 2 stages x 12KB
    __shared__ int   s_idx[2];
    __shared__ int   s_steal;
    __shared__ float shp[8];
    __shared__ float shc[8];
    __shared__ bool  is_last;

    const uint32_t sbase = smem_u32(&s_pose[0][0]);

    // ---- steal first two chunks ----
    if (tid == 0) {
        unsigned a = atomicAdd(&g_next, 1u);
        s_idx[0] = (a < nChunks) ? (int)a : -1;
        unsigned b2 = atomicAdd(&g_next, 1u);
        s_idx[1] = (b2 < nChunks) ? (int)b2 : -1;
    }
    __syncthreads();
    int cur = s_idx[0];
    int nxt = s_idx[1];

    if (cur >= 0) fill_stage(sbase,          pp, tp, cur, tid);
    cp_commit();
    if (nxt >= 0) fill_stage(sbase + 12288u, pp, tp, nxt, tid);
    cp_commit();

    float pose_s = 0.f, cls_s = 0.f;
    const float L = 0.05f;
    int s = 0;

    // loop-invariant smem row pointers (per stage)
    const float* sp0 = (const float*)&s_pose[0][0];
    const float* sp1 = (const float*)&s_pose[1][0];

    while (cur >= 0) {
        // class loads for current chunk: direct, coalesced, fly across the wait
        size_t b = ((size_t)cur << 8) + (size_t)tid;
        const float4* pc4 = (const float4*)pc + 4ull * b;
        const float4* tc4 = (const float4*)tc + 4ull * b;
        float4 x0 = __ldcs(pc4 + 0), x1 = __ldcs(pc4 + 1),
               x2 = __ldcs(pc4 + 2), x3 = __ldcs(pc4 + 3);
        float4 y0 = __ldcs(tc4 + 0), y1 = __ldcs(tc4 + 1),
               y2 = __ldcs(tc4 + 2), y3 = __ldcs(tc4 + 3);

        cp_wait1();           // this chunk's pose staged
        __syncthreads();

        // steal chunk-after-next while everyone computes (hidden ATOMG)
        if (tid == 0) {
            int n2 = -1;
            if (nxt >= 0) {
                unsigned a = atomicAdd(&g_next, 1u);
                if (a < nChunks) n2 = (int)a;
            }
            s_steal = n2;
        }

        // pose row from smem (24B/thread, <=2-way LDS conflict)
        const float* spf = s ? sp1 : sp0;
        const float2* mp = (const float2*)(spf + 6 * tid);
        const float2* mt = (const float2*)(spf + 1536 + 6 * tid);
        float2 a0 = mp[0], a1 = mp[1], a2 = mp[2];
        float2 b0 = mt[0], b1 = mt[1], b2 = mt[2];

        float sy1, cy1, sp1v, cp1v, sr1, cr1;
        __sincosf(a0.x, &sy1, &cy1);
        __sincosf(a0.y, &sp1v, &cp1v);
        __sincosf(a1.x, &sr1, &cr1);
        float sy2, cy2, sp2v, cp2v, sr2, cr2;
        __sincosf(b0.x, &sy2, &cy2);
        __sincosf(b0.y, &sp2v, &cp2v);
        __sincosf(b1.x, &sr2, &cr2);

        // class MSE in the MUFU shadow
        {
            float d;
            d = x0.x - y0.x; cls_s = fmaf(d, d, cls_s);
            d = x0.y - y0.y; cls_s = fmaf(d, d, cls_s);
            d = x0.z - y0.z; cls_s = fmaf(d, d, cls_s);
            d = x0.w - y0.w; cls_s = fmaf(d, d, cls_s);
            d = x1.x - y1.x; cls_s = fmaf(d, d, cls_s);
            d = x1.y - y1.y; cls_s = fmaf(d, d, cls_s);
            d = x1.z - y1.z; cls_s = fmaf(d, d, cls_s);
            d = x1.w - y1.w; cls_s = fmaf(d, d, cls_s);
            d = x2.x - y2.x; cls_s = fmaf(d, d, cls_s);
            d = x2.y - y2.y; cls_s = fmaf(d, d, cls_s);
            d = x2.z - y2.z; cls_s = fmaf(d, d, cls_s);
            d = x2.w - y2.w; cls_s = fmaf(d, d, cls_s);
            d = x3.x - y3.x; cls_s = fmaf(d, d, cls_s);
            d = x3.y - y3.y; cls_s = fmaf(d, d, cls_s);
            d = x3.z - y3.z; cls_s = fmaf(d, d, cls_s);
            d = x3.w - y3.w; cls_s = fmaf(d, d, cls_s);
        }

        // D = R_pred - R_gt, pre-scaled by L
        float D0 = cy1*cp1v                  - cy2*cp2v;
        float D1 = (cy1*sp1v*sr1 - sy1*cr1)  - (cy2*sp2v*sr2 - sy2*cr2);
        float D2 = (cy1*sp1v*cr1 + sy1*sr1)  - (cy2*sp2v*cr2 + sy2*sr2);
        float D3 = sy1*cp1v                  - sy2*cp2v;
        float D4 = (sy1*sp1v*sr1 + cy1*cr1)  - (sy2*sp2v*sr2 + cy2*cr2);
        float D5 = (sy1*sp1v*cr1 - cy1*sr1)  - (sy2*sp2v*cr2 - cy2*sr2);
        float D6 = -sp1v                     + sp2v;
        float D7 = cp1v*sr1                  - cp2v*sr2;
        float D8 = cp1v*cr1                  - cp2v*cr2;
        D0 *= L; D1 *= L; D2 *= L;
        D3 *= L; D4 *= L; D5 *= L;
        D6 *= L; D7 *= L; D8 *= L;

        float dt0 = a1.y - b1.y;
        float dt1 = a2.x - b2.x;
        float dt2 = a2.y - b2.y;

        float s2 = 0.f;
        #pragma unroll
        for (int ix = 0; ix < 2; ix++) {
            float fx = ix ? 1.f : -1.f;
            #pragma unroll
            for (int iy = 0; iy < 2; iy++) {
                float fy = iy ? 1.f : -1.f;
                #pragma unroll
                for (int iz = 0; iz < 2; iz++) {
                    float fz = iz ? 1.f : -1.f;
                    float vx = fmaf(fx, D0, fmaf(fy, D1, fmaf(fz, D2, dt0)));
                    float vy = fmaf(fx, D3, fmaf(fy, D4, fmaf(fz, D5, dt1)));
                    float vz = fmaf(fx, D6, fmaf(fy, D7, fmaf(fz, D8, dt2)));
                    float n2 = fmaf(vx, vx, fmaf(vy, vy, vz * vz));
                    s2 += fsqrt_approx(n2);
                }
            }
        }
        pose_s = fmaf(s2, 0.125f, pose_s);

        __syncthreads();      // stage reads done; s_steal visible

        int n2 = s_steal;
        if (n2 >= 0) fill_stage(sbase + (uint32_t)s * 12288u, pp, tp, n2, tid);
        cp_commit();          // exactly one commit per iteration (maybe empty)

        cur = nxt; nxt = n2; s ^= 1;
    }

    // ---- reduce ----
    #pragma unroll
    for (int o = 16; o > 0; o >>= 1) {
        pose_s += __shfl_down_sync(0xffffffffu, pose_s, o);
        cls_s  += __shfl_down_sync(0xffffffffu, cls_s,  o);
    }
    int lane = tid & 31;
    int w    = tid >> 5;
    if (lane == 0) { shp[w] = pose_s; shc[w] = cls_s; }
    __syncthreads();

    if (tid == 0) {
        float ap = 0.f, ac = 0.f;
        #pragma unroll
        for (int k = 0; k < 8; k++) { ap += shp[k]; ac += shc[k]; }
        atomicAdd(&g_acc[0], (double)ap);
        atomicAdd(&g_acc[1], (double)ac);
        __threadfence();
        unsigned int prev = atomicAdd(&g_done, 1u);
        is_last = (prev == gridDim.x - 1u);
    }
    __syncthreads();

    if (is_last && tid == 0) {
        double pose_mean = g_acc[0] / (double)B;
        double cls_mean  = g_acc[1] / ((double)B * 16.0);
        out[0] = (float)(pose_mean + cls_mean);
        out[1] = (float)pose_mean;
        out[2] = (float)cls_mean;
        g_acc[0] = 0.0;
        g_acc[1] = 0.0;
        g_next   = 0u;          // reset work counter for next replay
        __threadfence();
        g_done = 0u;
    }
}

extern "C" void kernel_launch(void* const* d_in, const int* in_sizes, int n_in,
                              void* d_out, int out_size) {
    const float* pp = (const float*)d_in[0];
    const float* pc = (const float*)d_in[1];
    const float* tp = (const float*)d_in[2];
    const float* tc = (const float*)d_in[3];
    int B = in_sizes[0] / 6;

    pose_loss_kernel<<<NBLOCKS, NTHREADS>>>(pp, pc, tp, tc, (float*)d_out, B);
}